// round 6
// baseline (speedup 1.0000x reference)
#include <cuda_runtime.h>
#include <cstdint>
#include <math.h>

#define BATCH 4096
#define N_GC  8192
#define N_PC  2048

#define TM 128
#define TN 128
#define KC 32                       // k floats per stage (128 B rows)
#define NCH (N_GC / KC)             // 256 chunks
#define STAGES 3
#define STAGE_BYTES ((TM + TN) * KC * 4)   // 32 KB
#define SMEM_SZ (STAGES * STAGE_BYTES)     // 96 KB

// -------- scratch (device globals: runtime alloc forbidden) ----------------
__device__ __align__(128) float g_At[(size_t)BATCH * N_GC];
__device__ __align__(128) float g_Bt[(size_t)N_PC  * N_GC];

// -------- helpers -----------------------------------------------------------
__device__ __forceinline__ float to_tf32(float x) {
    uint32_t r; asm("cvt.rna.tf32.f32 %0, %1;" : "=r"(r) : "f"(x));
    return __uint_as_float(r);
}
__device__ __forceinline__ float softplus_f(float x) {
    return fmaxf(x, 0.0f) + log1pf(expf(-fabsf(x)));
}
__device__ __forceinline__ uint32_t smem_u32(const void* p) {
    uint32_t a;
    asm("{ .reg .u64 t; cvta.to.shared.u64 t, %1; cvt.u32.u64 %0, t; }" : "=r"(a) : "l"(p));
    return a;
}
__device__ __forceinline__ void cp16(uint32_t dst, const void* src) {
    asm volatile("cp.async.cg.shared.global [%0], [%1], 16;" :: "r"(dst), "l"(src) : "memory");
}
__device__ __forceinline__ void cp_commit() { asm volatile("cp.async.commit_group;" ::: "memory"); }
template <int N> __device__ __forceinline__ void cp_wait() {
    asm volatile("cp.async.wait_group %0;" :: "n"(N) : "memory");
}
__device__ __forceinline__ void ldm4(uint32_t& r0, uint32_t& r1, uint32_t& r2, uint32_t& r3,
                                     uint32_t addr) {
    asm volatile("ldmatrix.sync.aligned.m8n8.x4.shared.b16 {%0,%1,%2,%3}, [%4];"
                 : "=r"(r0), "=r"(r1), "=r"(r2), "=r"(r3) : "r"(addr));
}
__device__ __forceinline__ void mma8(float* c, const uint32_t* a, uint32_t b0, uint32_t b1) {
    asm volatile(
        "mma.sync.aligned.m16n8k8.row.col.f32.tf32.tf32.f32 "
        "{%0,%1,%2,%3}, {%4,%5,%6,%7}, {%8,%9}, {%0,%1,%2,%3};"
        : "+f"(c[0]), "+f"(c[1]), "+f"(c[2]), "+f"(c[3])
        : "r"(a[0]), "r"(a[1]), "r"(a[2]), "r"(a[3]), "r"(b0), "r"(b1));
}

// -------- prologue kernels ---------------------------------------------------
__global__ void round_g_kernel(const float4* __restrict__ src) {
    size_t i = (size_t)blockIdx.x * blockDim.x + threadIdx.x;
    size_t stride = (size_t)gridDim.x * blockDim.x;
    float4* dst = reinterpret_cast<float4*>(g_At);
    const size_t n4 = (size_t)BATCH * N_GC / 4;
    for (size_t j = i; j < n4; j += stride) {
        float4 v = src[j];
        v.x = to_tf32(v.x); v.y = to_tf32(v.y); v.z = to_tf32(v.z); v.w = to_tf32(v.w);
        dst[j] = v;
    }
}
__global__ void build_w_kernel(const float4* __restrict__ wr, const float4* __restrict__ mk) {
    size_t i = (size_t)blockIdx.x * blockDim.x + threadIdx.x;
    size_t stride = (size_t)gridDim.x * blockDim.x;
    float4* dst = reinterpret_cast<float4*>(g_Bt);
    const size_t n4 = (size_t)N_PC * N_GC / 4;
    for (size_t j = i; j < n4; j += stride) {
        float4 w = wr[j]; float4 m = mk[j]; float4 o;
        o.x = to_tf32(softplus_f(w.x) * m.x);
        o.y = to_tf32(softplus_f(w.y) * m.y);
        o.z = to_tf32(softplus_f(w.z) * m.z);
        o.w = to_tf32(softplus_f(w.w) * m.w);
        dst[j] = o;
    }
}

// -------- GEMM: C[4096,2048] = At * Bt^T, tf32 mma.sync ----------------------
__global__ void __launch_bounds__(256, 2) purkinje_gemm(const float* __restrict__ b_pc,
                                                        float* __restrict__ out) {
    extern __shared__ char smem[];
    const uint32_t sb = smem_u32(smem);
    const int tid = threadIdx.x;
    const int wid = tid >> 5, l = tid & 31;
    const int n0 = blockIdx.x * TN;
    const int m0 = blockIdx.y * TM;
    const int wm = (wid >> 2) * 64;   // warp m offset in tile (0 or 64)
    const int wn = (wid & 3) * 32;    // warp n offset in tile (0..96)

    // ---- per-thread cp.async plan (8 x 16B per stage) ----
    const float* srcbase[8];
    uint32_t dstoff[8];
    #pragma unroll
    for (int j = 0; j < 8; ++j) {
        int idx = j * 256 + tid;      // 0..2047
        int r = idx >> 3, c = idx & 7;
        const float* base = (r < TM) ? (g_At + (size_t)(m0 + r) * N_GC)
                                     : (g_Bt + (size_t)(n0 + r - TM) * N_GC);
        srcbase[j] = base + c * 4;
        dstoff[j]  = (uint32_t)(r * 128 + ((c ^ (r & 7)) * 16));
    }

    // ---- ldmatrix lane addressing (lane-constant parts) ----
    const int arow   = (l & 7) | (l & 8);          // A fragment row within 16
    const int achunk = l >> 4;                     // 0/1: k halves
    const int brow   = (l & 7) | ((l & 16) >> 1);  // B fragment n-row within 16
    const int bchunk = (l >> 3) & 1;
    uint32_t baseA[4], baseB[2];
    #pragma unroll
    for (int mt = 0; mt < 4; ++mt) baseA[mt] = (uint32_t)((wm + mt * 16 + arow) * 128);
    #pragma unroll
    for (int p = 0; p < 2; ++p)    baseB[p]  = (uint32_t)((TM + wn + p * 16 + brow) * 128);
    uint32_t chA[4], chB[4];
    #pragma unroll
    for (int ks = 0; ks < 4; ++ks) {
        chA[ks] = (uint32_t)(((ks * 2 + achunk) ^ (l & 7)) * 16);
        chB[ks] = (uint32_t)(((ks * 2 + bchunk) ^ (l & 7)) * 16);
    }

    float acc[4][4][4];
    #pragma unroll
    for (int i = 0; i < 4; ++i)
        #pragma unroll
        for (int j = 0; j < 4; ++j)
            #pragma unroll
            for (int q = 0; q < 4; ++q) acc[i][j][q] = 0.0f;

    // ---- prologue: stages 0,1 ----
    #pragma unroll
    for (int s = 0; s < STAGES - 1; ++s) {
        uint32_t st = sb + s * STAGE_BYTES;
        #pragma unroll
        for (int j = 0; j < 8; ++j) cp16(st + dstoff[j], srcbase[j] + s * KC);
        cp_commit();
    }

    // ---- main loop ----
    for (int k = 0; k < NCH; ++k) {
        cp_wait<STAGES - 2>();          // chunk k resident (own groups)
        __syncthreads();                // everyone's chunk-k data visible; stage (k-1)%3 free

        if (k + STAGES - 1 < NCH) {
            uint32_t st = sb + ((k + STAGES - 1) % STAGES) * STAGE_BYTES;
            const int koff = (k + STAGES - 1) * KC;
            #pragma unroll
            for (int j = 0; j < 8; ++j) cp16(st + dstoff[j], srcbase[j] + koff);
        }
        cp_commit();                    // keep group count uniform

        const uint32_t st = sb + (k % STAGES) * STAGE_BYTES;
        #pragma unroll
        for (int ks = 0; ks < 4; ++ks) {
            uint32_t a[4][4];
            #pragma unroll
            for (int mt = 0; mt < 4; ++mt)
                ldm4(a[mt][0], a[mt][1], a[mt][2], a[mt][3], st + baseA[mt] + chA[ks]);
            #pragma unroll
            for (int p = 0; p < 2; ++p) {
                uint32_t b0, b1, b2, b3;
                ldm4(b0, b1, b2, b3, st + baseB[p] + chB[ks]);
                #pragma unroll
                for (int mt = 0; mt < 4; ++mt) {
                    mma8(acc[mt][2 * p],     a[mt], b0, b1);
                    mma8(acc[mt][2 * p + 1], a[mt], b2, b3);
                }
            }
        }
    }

    // ---- epilogue: bias + relu ----
    #pragma unroll
    for (int mt = 0; mt < 4; ++mt) {
        const int row = m0 + wm + mt * 16 + (l >> 2);
        #pragma unroll
        for (int nt = 0; nt < 4; ++nt) {
            const int col = n0 + wn + nt * 8 + (l & 3) * 2;
            float2 bv = *reinterpret_cast<const float2*>(&b_pc[col]);
            float2 o0, o1;
            o0.x = fmaxf(acc[mt][nt][0] + bv.x, 0.0f);
            o0.y = fmaxf(acc[mt][nt][1] + bv.y, 0.0f);
            o1.x = fmaxf(acc[mt][nt][2] + bv.x, 0.0f);
            o1.y = fmaxf(acc[mt][nt][3] + bv.y, 0.0f);
            *reinterpret_cast<float2*>(&out[(size_t)row * N_PC + col])       = o0;
            *reinterpret_cast<float2*>(&out[(size_t)(row + 8) * N_PC + col]) = o1;
        }
    }
}

// -------- launch --------------------------------------------------------------
extern "C" void kernel_launch(void* const* d_in, const int* in_sizes, int n_in,
                              void* d_out, int out_size) {
    (void)in_sizes; (void)n_in; (void)out_size;
    cudaFuncSetAttribute(purkinje_gemm, cudaFuncAttributeMaxDynamicSharedMemorySize, SMEM_SZ);
    round_g_kernel<<<1024, 256>>>(reinterpret_cast<const float4*>(d_in[0]));
    build_w_kernel<<<512, 256>>>(reinterpret_cast<const float4*>(d_in[1]),
                                 reinterpret_cast<const float4*>(d_in[3]));
    dim3 grid(N_PC / TN, BATCH / TM);
    purkinje_gemm<<<grid, 256, SMEM_SZ>>>(reinterpret_cast<const float*>(d_in[2]),
                                          reinterpret_cast<float*>(d_out));
}

// round 7
// speedup vs baseline: 1.0546x; 1.0546x over previous
#include <cuda_runtime.h>
#include <cstdint>
#include <math.h>

#define BATCH 4096
#define N_GC  8192
#define N_PC  2048

#define TM 128
#define TN 128
#define KC 32                        // k floats per stage (128 B rows)
#define NCH (N_GC / KC)              // 256 chunks
#define STAGES 3
#define STAGE_BYTES ((TM + TN) * KC * 4)   // 32 KB
#define SMEM_SZ (STAGES * STAGE_BYTES)     // 96 KB

// -------- scratch (device globals: runtime alloc forbidden) ----------------
__device__ __align__(128) float g_Bt[(size_t)N_PC * N_GC];

// -------- helpers -----------------------------------------------------------
__device__ __forceinline__ float to_tf32(float x) {
    uint32_t r; asm("cvt.rna.tf32.f32 %0, %1;" : "=r"(r) : "f"(x));
    return __uint_as_float(r);
}
__device__ __forceinline__ uint32_t cvt_rna_u(uint32_t x) {
    uint32_t r; asm("cvt.rna.tf32.f32 %0, %1;" : "=r"(r) : "f"(__uint_as_float(x)));
    return r;
}
__device__ __forceinline__ float softplus_f(float x) {
    return fmaxf(x, 0.0f) + log1pf(expf(-fabsf(x)));
}
__device__ __forceinline__ uint32_t smem_u32(const void* p) {
    uint32_t a;
    asm("{ .reg .u64 t; cvta.to.shared.u64 t, %1; cvt.u32.u64 %0, t; }" : "=r"(a) : "l"(p));
    return a;
}
__device__ __forceinline__ void cp16(uint32_t dst, const void* src) {
    asm volatile("cp.async.cg.shared.global [%0], [%1], 16;" :: "r"(dst), "l"(src) : "memory");
}
__device__ __forceinline__ void cp_commit() { asm volatile("cp.async.commit_group;" ::: "memory"); }
template <int N> __device__ __forceinline__ void cp_wait() {
    asm volatile("cp.async.wait_group %0;" :: "n"(N) : "memory");
}
__device__ __forceinline__ void ldm4(uint32_t& r0, uint32_t& r1, uint32_t& r2, uint32_t& r3,
                                     uint32_t addr) {
    asm volatile("ldmatrix.sync.aligned.m8n8.x4.shared.b16 {%0,%1,%2,%3}, [%4];"
                 : "=r"(r0), "=r"(r1), "=r"(r2), "=r"(r3) : "r"(addr));
}
__device__ __forceinline__ void mma8(float* c, const uint32_t* a, uint32_t b0, uint32_t b1) {
    asm volatile(
        "mma.sync.aligned.m16n8k8.row.col.f32.tf32.tf32.f32 "
        "{%0,%1,%2,%3}, {%4,%5,%6,%7}, {%8,%9}, {%0,%1,%2,%3};"
        : "+f"(c[0]), "+f"(c[1]), "+f"(c[2]), "+f"(c[3])
        : "r"(a[0]), "r"(a[1]), "r"(a[2]), "r"(a[3]), "r"(b0), "r"(b1));
}

// -------- prologue: B = tf32(softplus(W) * mask) -----------------------------
__global__ void build_w_kernel(const float4* __restrict__ wr, const float4* __restrict__ mk) {
    size_t i = (size_t)blockIdx.x * blockDim.x + threadIdx.x;
    size_t stride = (size_t)gridDim.x * blockDim.x;
    float4* dst = reinterpret_cast<float4*>(g_Bt);
    const size_t n4 = (size_t)N_PC * N_GC / 4;
    for (size_t j = i; j < n4; j += stride) {
        float4 w = wr[j]; float4 m = mk[j]; float4 o;
        o.x = to_tf32(softplus_f(w.x) * m.x);
        o.y = to_tf32(softplus_f(w.y) * m.y);
        o.z = to_tf32(softplus_f(w.z) * m.z);
        o.w = to_tf32(softplus_f(w.w) * m.w);
        dst[j] = o;
    }
}

// -------- GEMM: C[4096,2048] = g * Bt^T, tf32 mma.sync, 64x64 warp tiles -----
__global__ void __launch_bounds__(128, 2) purkinje_gemm(const float* __restrict__ g,
                                                        const float* __restrict__ b_pc,
                                                        float* __restrict__ out) {
    extern __shared__ char smem[];
    const uint32_t sb = smem_u32(smem);
    const int tid = threadIdx.x;
    const int wid = tid >> 5, l = tid & 31;
    const int n0 = blockIdx.x * TN;
    const int m0 = blockIdx.y * TM;
    const int wm = (wid & 1) * 64;       // warp m offset
    const int wn = (wid >> 1) * 64;      // warp n offset

    // ---- cp.async plan: 16 x 16B per thread per stage (A rows 0..127, B rows 128..255)
    const int tr = tid >> 3, tc = tid & 7;         // row-within-16-group, 16B chunk
    const uint32_t dbase = (uint32_t)(tr * 128 + ((tc ^ (tr & 7)) * 16));
    const float* aptr = g    + (size_t)(m0 + tr) * N_GC + tc * 4;
    const float* bptr = g_Bt + (size_t)(n0 + tr) * N_GC + tc * 4;

    // ---- ldmatrix lane addressing ----
    const int arow   = (l & 7) | (l & 8);
    const int achunk = l >> 4;
    const int brow   = (l & 7) | ((l & 16) >> 1);
    const int bchunk = (l >> 3) & 1;
    uint32_t baseA[4], baseB[4];
    #pragma unroll
    for (int mt = 0; mt < 4; ++mt) baseA[mt] = (uint32_t)((wm + mt * 16 + arow) * 128);
    #pragma unroll
    for (int p = 0; p < 4; ++p)    baseB[p]  = (uint32_t)((TM + wn + p * 16 + brow) * 128);
    uint32_t chA[4], chB[4];
    #pragma unroll
    for (int ks = 0; ks < 4; ++ks) {
        chA[ks] = (uint32_t)(((ks * 2 + achunk) ^ (l & 7)) * 16);
        chB[ks] = (uint32_t)(((ks * 2 + bchunk) ^ (l & 7)) * 16);
    }

    float acc[4][8][4];
    #pragma unroll
    for (int i = 0; i < 4; ++i)
        #pragma unroll
        for (int j = 0; j < 8; ++j)
            #pragma unroll
            for (int q = 0; q < 4; ++q) acc[i][j][q] = 0.0f;

    // ---- prologue: stages 0,1 ----
    #pragma unroll
    for (int s = 0; s < STAGES - 1; ++s) {
        const uint32_t st = sb + s * STAGE_BYTES;
        const int koff = s * KC;
        #pragma unroll
        for (int j = 0; j < 8; ++j) {
            cp16(st + dbase + j * 2048,         aptr + koff + (size_t)j * 16 * N_GC);
            cp16(st + dbase + 16384 + j * 2048, bptr + koff + (size_t)j * 16 * N_GC);
        }
        cp_commit();
    }

    // ---- main loop ----
    for (int k = 0; k < NCH; ++k) {
        cp_wait<STAGES - 2>();
        __syncthreads();

        if (k + STAGES - 1 < NCH) {
            const uint32_t st = sb + ((k + STAGES - 1) % STAGES) * STAGE_BYTES;
            const int koff = (k + STAGES - 1) * KC;
            #pragma unroll
            for (int j = 0; j < 8; ++j) {
                cp16(st + dbase + j * 2048,         aptr + koff + (size_t)j * 16 * N_GC);
                cp16(st + dbase + 16384 + j * 2048, bptr + koff + (size_t)j * 16 * N_GC);
            }
        }
        cp_commit();

        const uint32_t st = sb + (k % STAGES) * STAGE_BYTES;
        #pragma unroll
        for (int ks = 0; ks < 4; ++ks) {
            uint32_t a[4][4];
            #pragma unroll
            for (int mt = 0; mt < 4; ++mt) {
                ldm4(a[mt][0], a[mt][1], a[mt][2], a[mt][3], st + baseA[mt] + chA[ks]);
                a[mt][0] = cvt_rna_u(a[mt][0]);  // A comes straight from fp32 g_in:
                a[mt][1] = cvt_rna_u(a[mt][1]);  // round to tf32 (RNA) in-register
                a[mt][2] = cvt_rna_u(a[mt][2]);
                a[mt][3] = cvt_rna_u(a[mt][3]);
            }
            #pragma unroll
            for (int p = 0; p < 4; ++p) {
                uint32_t b0, b1, b2, b3;
                ldm4(b0, b1, b2, b3, st + baseB[p] + chB[ks]);
                #pragma unroll
                for (int mt = 0; mt < 4; ++mt) {
                    mma8(acc[mt][2 * p],     a[mt], b0, b1);
                    mma8(acc[mt][2 * p + 1], a[mt], b2, b3);
                }
            }
        }
    }

    // ---- epilogue: bias + relu ----
    #pragma unroll
    for (int mt = 0; mt < 4; ++mt) {
        const int row = m0 + wm + mt * 16 + (l >> 2);
        #pragma unroll
        for (int nt = 0; nt < 8; ++nt) {
            const int col = n0 + wn + nt * 8 + (l & 3) * 2;
            float2 bv = *reinterpret_cast<const float2*>(&b_pc[col]);
            float2 o0, o1;
            o0.x = fmaxf(acc[mt][nt][0] + bv.x, 0.0f);
            o0.y = fmaxf(acc[mt][nt][1] + bv.y, 0.0f);
            o1.x = fmaxf(acc[mt][nt][2] + bv.x, 0.0f);
            o1.y = fmaxf(acc[mt][nt][3] + bv.y, 0.0f);
            *reinterpret_cast<float2*>(&out[(size_t)row * N_PC + col])       = o0;
            *reinterpret_cast<float2*>(&out[(size_t)(row + 8) * N_PC + col]) = o1;
        }
    }
}

// -------- launch --------------------------------------------------------------
extern "C" void kernel_launch(void* const* d_in, const int* in_sizes, int n_in,
                              void* d_out, int out_size) {
    (void)in_sizes; (void)n_in; (void)out_size;
    cudaFuncSetAttribute(purkinje_gemm, cudaFuncAttributeMaxDynamicSharedMemorySize, SMEM_SZ);
    build_w_kernel<<<512, 256>>>(reinterpret_cast<const float4*>(d_in[1]),
                                 reinterpret_cast<const float4*>(d_in[3]));
    dim3 grid(N_PC / TN, BATCH / TM);
    purkinje_gemm<<<grid, 128, SMEM_SZ>>>(reinterpret_cast<const float*>(d_in[0]),
                                          reinterpret_cast<const float*>(d_in[2]),
                                          reinterpret_cast<float*>(d_out));
}